// round 1
// baseline (speedup 1.0000x reference)
#include <cuda_runtime.h>
#include <math.h>

#define TWO_PI_F 6.28318530717958647692f
#define PI_F     3.14159265358979323846f
#define INV_PI2_F 0.63661977236758134308f  // 2/pi

#define PSZ   8
#define HH    64
#define WW    64
#define HPN   57
#define NPP   (HPN*HPN)        // 3249
#define NBATCH 2
#define NPTOT (NBATCH*NPP)     // 6498
#define NV    31
#define CINN  32
#define NPIX  (HH*WW)          // 4096
#define NSTAT 8192             // B*H*W elements per BN channel

// ---------------- device scratch (no allocations allowed) ----------------
__device__ float  g_y[NBATCH*3*NPIX];
__device__ float4 g_xr4[NBATCH*NPIX];
__device__ float  g_params[NBATCH*5*NPP];
__device__ float  g_smoothed[NBATCH*3*NPIX];
__device__ float  g_gb[NBATCH*NPIX];
__device__ float  g_yb[NBATCH*NPIX];
__device__ float  g_yi[NBATCH*NPIX];
__device__ float  g_stats[16]; // [0..2] conv sum, [3..5] conv sumsq, [6,7] yb sum/ss, [8,9] yi sum/ss

// ---------------- helpers ----------------
__device__ __forceinline__ float mod2pi(float v) {
    float m = fmodf(v, TWO_PI_F);
    return (m < 0.0f) ? m + TWO_PI_F : m;
}
__device__ __forceinline__ float pow35(float u) {
    float u2 = u*u, u4 = u2*u2, u8 = u4*u4, u16 = u8*u8;
    return u16*u16*u2*u;  // u^35
}
__device__ __forceinline__ float silu(float v) {
    return v / (1.0f + expf(-v));
}

struct Cand {
    float s1,c1,s2,c2,s3,c3,s4,c4;
    float sg13, sg42, off13, off42;
    float x0, y0;
};

__device__ __forceinline__ Cand make_cand(const float cp[5]) {
    Cand K;
    K.x0 = cp[3]; K.y0 = cp[4];
    float m0 = mod2pi(cp[0]), m1 = mod2pi(cp[1]), m2 = mod2pi(cp[2]);
    float lo = fminf(m0, m1), hi = fmaxf(m0, m1);
    float a1 = fminf(lo, m2);
    float a3 = fmaxf(hi, m2);
    float a2 = fmaxf(lo, fminf(hi, m2));
    float hm = mod2pi(0.5f*(a1 - a3));
    float a4 = 0.5f*(a1 + a3) + ((hm >= PI_F) ? PI_F : 0.0f);
    float d13 = mod2pi(a3 - a1);
    float d42 = mod2pi(a2 - a4);
    K.sg13 = (d13 < PI_F) ? 1.0f : -1.0f;
    K.sg42 = (d42 < PI_F) ? 1.0f : -1.0f;
    K.off13 = 0.1f * pow35(d13 / PI_F - 1.0f);
    K.off42 = 0.1f * pow35(d42 / PI_F - 1.0f);
    sincosf(a1, &K.s1, &K.c1);
    sincosf(a2, &K.s2, &K.c2);
    sincosf(a3, &K.s3, &K.c3);
    sincosf(a4, &K.s4, &K.c4);
    return K;
}

__device__ __forceinline__ void dists_at(const Cand& K, float dx, float t1, float t2,
                                         float t3, float t4, float& d13v, float& d42v) {
    float l1 = fmaf(-K.s1, dx, t1);
    float l2 = fmaf(-K.s2, dx, t2);
    float l3 = fmaf(-K.s3, dx, t3);
    float l4 = fmaf(-K.s4, dx, t4);
    d13v = fmaf(K.sg13, fminf(K.sg13*l1, -K.sg13*l3), K.off13);
    d42v = fmaf(K.sg42, fminf(K.sg42*l4, -K.sg42*l2), K.off42);
}

__device__ __forceinline__ float cand_range(int ip, int q) {
    return (ip < 3) ? (float)q * (TWO_PI_F / 31.0f)
                    : (-3.0f + (float)q * 0.2f);
}

// ---------------- kernels ----------------
__global__ void k_zero() {
    int t = blockIdx.x * blockDim.x + threadIdx.x;
    int stride = gridDim.x * blockDim.x;
    if (t < 16) g_stats[t] = 0.0f;
    for (int i = t; i < NBATCH*5*NPP;  i += stride) g_params[i]   = 0.0f;
    for (int i = t; i < NBATCH*3*NPIX; i += stride) g_smoothed[i] = 0.0f;
    for (int i = t; i < NBATCH*NPIX;   i += stride) g_gb[i]       = 0.0f;
}

__global__ void k_conv(const float* __restrict__ x, const float* __restrict__ rw) {
    // grid: (B*3)*16 blocks of 256; one (b,o) channel per 16-block group
    int bo = blockIdx.x >> 4;
    int chunk = blockIdx.x & 15;
    int b = bo / 3, o = bo % 3;
    int pix = chunk * 256 + threadIdx.x;
    const float* xp = x + (size_t)b * CINN * NPIX + pix;
    float acc = 0.0f;
    #pragma unroll
    for (int c = 0; c < CINN; c++)
        acc = fmaf(xp[c * NPIX], rw[o * CINN + c], acc);
    g_y[(b*3 + o) * NPIX + pix] = acc;

    __shared__ float s1[256], s2[256];
    s1[threadIdx.x] = acc; s2[threadIdx.x] = acc * acc;
    __syncthreads();
    for (int s = 128; s > 0; s >>= 1) {
        if (threadIdx.x < s) { s1[threadIdx.x] += s1[threadIdx.x+s]; s2[threadIdx.x] += s2[threadIdx.x+s]; }
        __syncthreads();
    }
    if (threadIdx.x == 0) {
        atomicAdd(&g_stats[o],     s1[0]);
        atomicAdd(&g_stats[3 + o], s2[0]);
    }
}

__global__ void k_bnsilu(const float* __restrict__ gamma, const float* __restrict__ beta) {
    int t = blockIdx.x * 256 + threadIdx.x;   // 0 .. 8191
    int b = t >> 12, pix = t & (NPIX - 1);
    float v[3];
    #pragma unroll
    for (int c = 0; c < 3; c++) {
        float m   = g_stats[c]     * (1.0f / NSTAT);
        float var = g_stats[3 + c] * (1.0f / NSTAT) - m * m;
        float y   = g_y[(b*3 + c) * NPIX + pix];
        float n   = gamma[c] * (y - m) * rsqrtf(var + 1e-5f) + beta[c];
        v[c] = silu(n);
    }
    g_xr4[t] = make_float4(v[0], v[1], v[2], 0.0f);
}

__global__ void __launch_bounds__(248) k_step(int ip) {
    int tid = threadIdx.x;
    int lp = tid / NV, q = tid - lp * NV;
    int P = blockIdx.x * 8 + lp;
    __shared__ float sLoss[248];

    bool valid = (P < NPTOT);
    int b = 0, pp = 0, hp = 0, wp = 0;
    float p[5] = {0,0,0,0,0};
    float score = 3.4e38f;

    if (valid) {
        b = P / NPP; pp = P - b * NPP; hp = pp / HPN; wp = pp - hp * HPN;
        #pragma unroll
        for (int j = 0; j < 5; j++) p[j] = g_params[(b*5 + j) * NPP + pp];

        float cp[5];
        #pragma unroll
        for (int j = 0; j < 5; j++) cp[j] = p[j];
        cp[ip] += cand_range(ip, q);

        Cand K = make_cand(cp);
        const float4* tile = g_xr4 + b * NPIX + hp * WW + wp;

        float sw0=0,sw1=0,sw2=0;
        float cn00=0,cn01=0,cn02=0, cn10=0,cn11=0,cn12=0, cn20=0,cn21=0,cn22=0;
        float G00=0,G11=0,G22=0,G01=0,G02=0,G12=0;

        #pragma unroll 1
        for (int xr = 0; xr < PSZ; xr++) {
            float dy = (-1.0f + (float)xr * (2.0f/7.0f)) - K.y0;
            float t1 = K.c1*dy, t2 = K.c2*dy, t3 = K.c3*dy, t4 = K.c4*dy;
            const float4* row = tile + xr * WW;
            #pragma unroll
            for (int yc = 0; yc < PSZ; yc++) {
                float dx = (-1.0f + (float)yc * (2.0f/7.0f)) - K.x0;
                float d13v, d42v;
                dists_at(K, dx, t1, t2, t3, t4, d13v, d42v);
                float h0 = 0.5f * (1.0f + INV_PI2_F * atanf(d13v / 0.01f));
                float h1 = 0.5f * (1.0f + INV_PI2_F * atanf(d42v / 0.01f));
                float w0 = 1.0f - h0;
                float w1 = h0 * (1.0f - h1);
                float w2 = h0 * h1;
                float4 img = __ldg(row + yc);
                sw0 += w0; sw1 += w1; sw2 += w2;
                cn00 = fmaf(img.x, w0, cn00); cn01 = fmaf(img.x, w1, cn01); cn02 = fmaf(img.x, w2, cn02);
                cn10 = fmaf(img.y, w0, cn10); cn11 = fmaf(img.y, w1, cn11); cn12 = fmaf(img.y, w2, cn12);
                cn20 = fmaf(img.z, w0, cn20); cn21 = fmaf(img.z, w1, cn21); cn22 = fmaf(img.z, w2, cn22);
                G00 = fmaf(w0, w0, G00); G11 = fmaf(w1, w1, G11); G22 = fmaf(w2, w2, G22);
                G01 = fmaf(w0, w1, G01); G02 = fmaf(w0, w2, G02); G12 = fmaf(w1, w2, G12);
            }
        }
        float i0 = 1.0f / (sw0 + 1e-10f);
        float i1 = 1.0f / (sw1 + 1e-10f);
        float i2 = 1.0f / (sw2 + 1e-10f);
        score = 0.0f;
        #pragma unroll
        for (int c = 0; c < 3; c++) {
            float n0 = (c==0)?cn00:((c==1)?cn10:cn20);
            float n1 = (c==0)?cn01:((c==1)?cn11:cn21);
            float n2 = (c==0)?cn02:((c==1)?cn12:cn22);
            float c0 = n0*i0, c1 = n1*i1, c2 = n2*i2;
            float quad = c0*c0*G00 + c1*c1*G11 + c2*c2*G22
                       + 2.0f*(c0*c1*G01 + c0*c2*G02 + c1*c2*G12);
            score += quad - 2.0f*(c0*n0 + c1*n1 + c2*n2);
        }
    }
    sLoss[tid] = score;
    __syncthreads();

    if (valid && q == 0) {
        int best = 0;
        float bl = sLoss[lp * NV];
        #pragma unroll
        for (int k = 1; k < NV; k++) {
            float v = sLoss[lp * NV + k];
            if (v < bl) { bl = v; best = k; }
        }
        g_params[(b*5 + ip) * NPP + pp] = p[ip] + cand_range(ip, best);
    }
}

__global__ void k_final() {
    int P = blockIdx.x * blockDim.x + threadIdx.x;
    if (P >= NPTOT) return;
    int b = P / NPP, pp = P - b * NPP;
    int hp = pp / HPN, wp = pp - hp * HPN;

    float cp[5];
    #pragma unroll
    for (int j = 0; j < 5; j++) cp[j] = g_params[(b*5 + j) * NPP + pp];
    Cand K = make_cand(cp);
    const float4* tile = g_xr4 + b * NPIX + hp * WW + wp;

    // pass 1: wedge sums + color numerators
    float sw[3] = {0,0,0};
    float cn[3][3] = {{0,0,0},{0,0,0},{0,0,0}};
    #pragma unroll 1
    for (int xr = 0; xr < PSZ; xr++) {
        float dy = (-1.0f + (float)xr * (2.0f/7.0f)) - K.y0;
        float t1 = K.c1*dy, t2 = K.c2*dy, t3 = K.c3*dy, t4 = K.c4*dy;
        const float4* row = tile + xr * WW;
        #pragma unroll
        for (int yc = 0; yc < PSZ; yc++) {
            float dx = (-1.0f + (float)yc * (2.0f/7.0f)) - K.x0;
            float d13v, d42v;
            dists_at(K, dx, t1, t2, t3, t4, d13v, d42v);
            float h0 = 0.5f * (1.0f + INV_PI2_F * atanf(d13v / 0.01f));
            float h1 = 0.5f * (1.0f + INV_PI2_F * atanf(d42v / 0.01f));
            float w0 = 1.0f - h0, w1 = h0 * (1.0f - h1), w2 = h0 * h1;
            float4 img = __ldg(row + yc);
            sw[0] += w0; sw[1] += w1; sw[2] += w2;
            cn[0][0] = fmaf(img.x,w0,cn[0][0]); cn[0][1] = fmaf(img.x,w1,cn[0][1]); cn[0][2] = fmaf(img.x,w2,cn[0][2]);
            cn[1][0] = fmaf(img.y,w0,cn[1][0]); cn[1][1] = fmaf(img.y,w1,cn[1][1]); cn[1][2] = fmaf(img.y,w2,cn[1][2]);
            cn[2][0] = fmaf(img.z,w0,cn[2][0]); cn[2][1] = fmaf(img.z,w1,cn[2][1]); cn[2][2] = fmaf(img.z,w2,cn[2][2]);
        }
    }
    float col[3][3];
    #pragma unroll
    for (int k = 0; k < 3; k++) {
        float inv = 1.0f / (sw[k] + 1e-10f);
        col[0][k] = cn[0][k] * inv;
        col[1][k] = cn[1][k] * inv;
        col[2][k] = cn[2][k] * inv;
    }

    // pass 2: reconstruct patches + boundary map, scatter-add (fold)
    #pragma unroll 1
    for (int xr = 0; xr < PSZ; xr++) {
        float dy = (-1.0f + (float)xr * (2.0f/7.0f)) - K.y0;
        float t1 = K.c1*dy, t2 = K.c2*dy, t3 = K.c3*dy, t4 = K.c4*dy;
        int hh = xr + hp;
        #pragma unroll
        for (int yc = 0; yc < PSZ; yc++) {
            float dx = (-1.0f + (float)yc * (2.0f/7.0f)) - K.x0;
            float d13v, d42v;
            dists_at(K, dx, t1, t2, t3, t4, d13v, d42v);
            float h0 = 0.5f * (1.0f + INV_PI2_F * atanf(d13v / 0.01f));
            float h1 = 0.5f * (1.0f + INV_PI2_F * atanf(d42v / 0.01f));
            float w0 = 1.0f - h0, w1 = h0 * (1.0f - h1), w2 = h0 * h1;
            int ww_ = yc + wp;
            int opix = hh * WW + ww_;
            #pragma unroll
            for (int c = 0; c < 3; c++) {
                float pv = w0*col[c][0] + w1*col[c][1] + w2*col[c][2];
                atomicAdd(&g_smoothed[(b*3 + c) * NPIX + opix], pv);
            }
            // boundaries
            float d1 = d13v, d2 = d42v;
            float mad = (d1 < 0.0f) ? -d1
                      : ((d2 < 0.0f) ? fminf(d1, -d2) : fminf(d1, d2));
            float r = mad / 0.05f;
            float lb = 1.0f / (1.0f + r * r);
            atomicAdd(&g_gb[b * NPIX + opix], lb);
        }
    }
}

__global__ void k_post1(const float* __restrict__ fbw, const float* __restrict__ fiw) {
    int t = blockIdx.x * 256 + threadIdx.x;   // 0..8191
    int b = t >> 12, pix = t & (NPIX - 1);
    int h = pix >> 6, w = pix & 63;
    int ch = min(min(h + 1, HH - h), PSZ);
    int cw = min(min(w + 1, WW - w), PSZ);
    float inv = 1.0f / (float)(ch * cw);

    float sm0 = g_smoothed[(b*3 + 0) * NPIX + pix] * inv;
    float sm1 = g_smoothed[(b*3 + 1) * NPIX + pix] * inv;
    float sm2 = g_smoothed[(b*3 + 2) * NPIX + pix] * inv;
    float yi = sm0 * fiw[0] + sm1 * fiw[1] + sm2 * fiw[2];
    float gbv = g_gb[t] * inv;
    float yb = gbv * fbw[0] + gbv * fbw[1] + gbv * fbw[2];
    g_yi[t] = yi;
    g_yb[t] = yb;

    __shared__ float sA[256], sB[256];
    // yb stats
    sA[threadIdx.x] = yb; sB[threadIdx.x] = yb * yb;
    __syncthreads();
    for (int s = 128; s > 0; s >>= 1) {
        if (threadIdx.x < s) { sA[threadIdx.x] += sA[threadIdx.x+s]; sB[threadIdx.x] += sB[threadIdx.x+s]; }
        __syncthreads();
    }
    if (threadIdx.x == 0) { atomicAdd(&g_stats[6], sA[0]); atomicAdd(&g_stats[7], sB[0]); }
    __syncthreads();
    // yi stats
    sA[threadIdx.x] = yi; sB[threadIdx.x] = yi * yi;
    __syncthreads();
    for (int s = 128; s > 0; s >>= 1) {
        if (threadIdx.x < s) { sA[threadIdx.x] += sA[threadIdx.x+s]; sB[threadIdx.x] += sB[threadIdx.x+s]; }
        __syncthreads();
    }
    if (threadIdx.x == 0) { atomicAdd(&g_stats[8], sA[0]); atomicAdd(&g_stats[9], sB[0]); }
}

__global__ void k_out(float* __restrict__ out,
                      const float* __restrict__ fbg, const float* __restrict__ fbb,
                      const float* __restrict__ fig, const float* __restrict__ fib) {
    int t = blockIdx.x * 256 + threadIdx.x;  // 0..8191
    float mb = g_stats[6] * (1.0f / NSTAT);
    float vb = g_stats[7] * (1.0f / NSTAT) - mb * mb;
    float nb = fbg[0] * (g_yb[t] - mb) * rsqrtf(vb + 1e-5f) + fbb[0];
    out[t] = silu(nb);

    float mi = g_stats[8] * (1.0f / NSTAT);
    float vi = g_stats[9] * (1.0f / NSTAT) - mi * mi;
    float ni = fig[0] * (g_yi[t] - mi) * rsqrtf(vi + 1e-5f) + fib[0];
    out[NBATCH * NPIX + t] = silu(ni);
}

// ---------------- launch ----------------
extern "C" void kernel_launch(void* const* d_in, const int* in_sizes, int n_in,
                              void* d_out, int out_size) {
    const float* x   = (const float*)d_in[0];
    const float* rw  = (const float*)d_in[1];
    const float* rg  = (const float*)d_in[2];
    const float* rb  = (const float*)d_in[3];
    const float* fbw = (const float*)d_in[4];
    const float* fbg = (const float*)d_in[5];
    const float* fbb = (const float*)d_in[6];
    const float* fiw = (const float*)d_in[7];
    const float* fig = (const float*)d_in[8];
    const float* fib = (const float*)d_in[9];
    float* out = (float*)d_out;

    k_zero<<<64, 256>>>();
    k_conv<<<NBATCH * 3 * 16, 256>>>(x, rw);
    k_bnsilu<<<32, 256>>>(rg, rb);
    for (int i = 0; i < 5; i++)
        k_step<<<(NPTOT + 7) / 8, 248>>>(i);
    k_final<<<(NPTOT + 255) / 256, 256>>>();
    k_post1<<<32, 256>>>(fbw, fiw);
    k_out<<<32, 256>>>(out, fbg, fbb, fig, fib);
}

// round 2
// speedup vs baseline: 1.2944x; 1.2944x over previous
#include <cuda_runtime.h>
#include <math.h>

#define TWO_PI_F 6.28318530717958647692f
#define PI_F     3.14159265358979323846f
#define INV_PI_F 0.31830988618367094f
#define INV_PI2_F 0.63661977236758134308f  // 2/pi

#define PSZ   8
#define HH    64
#define WW    64
#define HPN   57
#define NPP   (HPN*HPN)        // 3249
#define NBATCH 2
#define NPTOT (NBATCH*NPP)     // 6498
#define NV    31
#define CINN  32
#define NPIX  (HH*WW)          // 4096
#define NSTAT 8192             // B*H*W elements per BN channel

// ---------------- device scratch (no allocations allowed) ----------------
__device__ float  g_y[NBATCH*3*NPIX];
__device__ float4 g_xr4[NBATCH*NPIX];
__device__ float4 g_ps4[NPTOT];       // per-patch channel sums
__device__ float  g_params[NBATCH*5*NPP];
__device__ float  g_smoothed[NBATCH*3*NPIX];
__device__ float  g_gb[NBATCH*NPIX];
__device__ float  g_yb[NBATCH*NPIX];
__device__ float  g_yi[NBATCH*NPIX];
__device__ float  g_stats[16];

// ---------------- helpers ----------------
__device__ __forceinline__ float mod2pi(float v) {
    float m = fmodf(v, TWO_PI_F);
    return (m < 0.0f) ? m + TWO_PI_F : m;
}
__device__ __forceinline__ float pow35(float u) {
    float u2 = u*u, u4 = u2*u2, u8 = u4*u4, u16 = u8*u8;
    return u16*u16*u2*u;
}
__device__ __forceinline__ float silu(float v) {
    return v / (1.0f + expf(-v));
}

// h = 0.5 + (1/pi) * atan(d / 0.01)   -- fast minimax version
__device__ __forceinline__ float fast_h(float d) {
    float x  = d * 100.0f;
    float ax = fabsf(x);
    float inv;
    asm("rcp.approx.f32 %0, %1;" : "=f"(inv) : "f"(ax));
    bool  big = ax > 1.0f;
    float t = big ? inv : ax;
    float s = t * t;
    float p =          -0.01172120f;
    p = fmaf(p, s,  0.05265332f);
    p = fmaf(p, s, -0.11643287f);
    p = fmaf(p, s,  0.19354346f);
    p = fmaf(p, s, -0.33262347f);
    p = fmaf(p, s,  0.99997726f);
    float r = t * p;
    r = big ? (1.5707963267948966f - r) : r;
    r = (x < 0.0f) ? -r : r;
    return fmaf(INV_PI_F, r, 0.5f);
}

struct Cand {
    float s1,c1,s2,c2,s3,c3,s4,c4;
    float sg13, sg42, off13, off42;
    float x0, y0;
};

__device__ __forceinline__ Cand make_cand(const float cp[5]) {
    Cand K;
    K.x0 = cp[3]; K.y0 = cp[4];
    float m0 = mod2pi(cp[0]), m1 = mod2pi(cp[1]), m2 = mod2pi(cp[2]);
    float lo = fminf(m0, m1), hi = fmaxf(m0, m1);
    float a1 = fminf(lo, m2);
    float a3 = fmaxf(hi, m2);
    float a2 = fmaxf(lo, fminf(hi, m2));
    float hm = mod2pi(0.5f*(a1 - a3));
    float a4 = 0.5f*(a1 + a3) + ((hm >= PI_F) ? PI_F : 0.0f);
    float d13 = mod2pi(a3 - a1);
    float d42 = mod2pi(a2 - a4);
    K.sg13 = (d13 < PI_F) ? 1.0f : -1.0f;
    K.sg42 = (d42 < PI_F) ? 1.0f : -1.0f;
    K.off13 = 0.1f * pow35(d13 / PI_F - 1.0f);
    K.off42 = 0.1f * pow35(d42 / PI_F - 1.0f);
    sincosf(a1, &K.s1, &K.c1);
    sincosf(a2, &K.s2, &K.c2);
    sincosf(a3, &K.s3, &K.c3);
    sincosf(a4, &K.s4, &K.c4);
    return K;
}

__device__ __forceinline__ void dists_at(const Cand& K, float dx, float t1, float t2,
                                         float t3, float t4, float& d13v, float& d42v) {
    float l1 = fmaf(-K.s1, dx, t1);
    float l2 = fmaf(-K.s2, dx, t2);
    float l3 = fmaf(-K.s3, dx, t3);
    float l4 = fmaf(-K.s4, dx, t4);
    d13v = fmaf(K.sg13, fminf(K.sg13*l1, -K.sg13*l3), K.off13);
    d42v = fmaf(K.sg42, fminf(K.sg42*l4, -K.sg42*l2), K.off42);
}

__device__ __forceinline__ float cand_range(int ip, int q) {
    return (ip < 3) ? (float)q * (TWO_PI_F / 31.0f)
                    : (-3.0f + (float)q * 0.2f);
}

// ---------------- kernels ----------------
__global__ void k_zero() {
    int t = blockIdx.x * blockDim.x + threadIdx.x;
    int stride = gridDim.x * blockDim.x;
    if (t < 16) g_stats[t] = 0.0f;
    for (int i = t; i < NBATCH*5*NPP;  i += stride) g_params[i]   = 0.0f;
    for (int i = t; i < NBATCH*3*NPIX; i += stride) g_smoothed[i] = 0.0f;
    for (int i = t; i < NBATCH*NPIX;   i += stride) g_gb[i]       = 0.0f;
}

__global__ void k_conv(const float* __restrict__ x, const float* __restrict__ rw) {
    int bo = blockIdx.x >> 4;
    int chunk = blockIdx.x & 15;
    int b = bo / 3, o = bo % 3;
    int pix = chunk * 256 + threadIdx.x;
    const float* xp = x + (size_t)b * CINN * NPIX + pix;
    float acc = 0.0f;
    #pragma unroll
    for (int c = 0; c < CINN; c++)
        acc = fmaf(xp[c * NPIX], rw[o * CINN + c], acc);
    g_y[(b*3 + o) * NPIX + pix] = acc;

    __shared__ float s1[256], s2[256];
    s1[threadIdx.x] = acc; s2[threadIdx.x] = acc * acc;
    __syncthreads();
    for (int s = 128; s > 0; s >>= 1) {
        if (threadIdx.x < s) { s1[threadIdx.x] += s1[threadIdx.x+s]; s2[threadIdx.x] += s2[threadIdx.x+s]; }
        __syncthreads();
    }
    if (threadIdx.x == 0) {
        atomicAdd(&g_stats[o],     s1[0]);
        atomicAdd(&g_stats[3 + o], s2[0]);
    }
}

__global__ void k_bnsilu(const float* __restrict__ gamma, const float* __restrict__ beta) {
    int t = blockIdx.x * 256 + threadIdx.x;
    int b = t >> 12, pix = t & (NPIX - 1);
    float v[3];
    #pragma unroll
    for (int c = 0; c < 3; c++) {
        float m   = g_stats[c]     * (1.0f / NSTAT);
        float var = g_stats[3 + c] * (1.0f / NSTAT) - m * m;
        float y   = g_y[(b*3 + c) * NPIX + pix];
        float n   = gamma[c] * (y - m) * rsqrtf(var + 1e-5f) + beta[c];
        v[c] = silu(n);
    }
    g_xr4[t] = make_float4(v[0], v[1], v[2], 0.0f);
}

// per-patch channel sums (candidate-independent)
__global__ void k_psum() {
    int P = blockIdx.x * blockDim.x + threadIdx.x;
    if (P >= NPTOT) return;
    int b = P / NPP, pp = P - b * NPP;
    int hp = pp / HPN, wp = pp - hp * HPN;
    const float4* tile = g_xr4 + b * NPIX + hp * WW + wp;
    float s0 = 0.0f, s1 = 0.0f, s2 = 0.0f;
    #pragma unroll 1
    for (int xr = 0; xr < PSZ; xr++) {
        const float4* row = tile + xr * WW;
        #pragma unroll
        for (int yc = 0; yc < PSZ; yc++) {
            float4 v = __ldg(row + yc);
            s0 += v.x; s1 += v.y; s2 += v.z;
        }
    }
    g_ps4[P] = make_float4(s0, s1, s2, 0.0f);
}

__global__ void __launch_bounds__(248) k_step(int ip) {
    int tid = threadIdx.x;
    int lp = tid / NV, q = tid - lp * NV;
    int P = blockIdx.x * 8 + lp;
    __shared__ float sLoss[248];

    bool valid = (P < NPTOT);
    int b = 0, pp = 0;
    float p[5] = {0,0,0,0,0};
    float score = 3.4e38f;

    if (valid) {
        b = P / NPP; pp = P - b * NPP;
        int hp = pp / HPN, wp = pp - hp * HPN;
        #pragma unroll
        for (int j = 0; j < 5; j++) p[j] = g_params[(b*5 + j) * NPP + pp];

        float cp[5];
        #pragma unroll
        for (int j = 0; j < 5; j++) cp[j] = p[j];
        cp[ip] += cand_range(ip, q);

        Cand K = make_cand(cp);
        const float4* tile = g_xr4 + b * NPIX + hp * WW + wp;
        float4 S = __ldg(&g_ps4[P]);

        float dxv[PSZ];
        #pragma unroll
        for (int yc = 0; yc < PSZ; yc++)
            dxv[yc] = (-1.0f + (float)yc * (2.0f/7.0f)) - K.x0;

        // reduced accumulator set (wedge 2 eliminated via w0+w1+w2=1)
        float sw0=0.f, sw1=0.f;
        float cn00=0.f,cn01=0.f, cn10=0.f,cn11=0.f, cn20=0.f,cn21=0.f;
        float G00=0.f,G11=0.f,G01=0.f;

        #pragma unroll 1
        for (int xr = 0; xr < PSZ; xr++) {
            float dy = (-1.0f + (float)xr * (2.0f/7.0f)) - K.y0;
            float t1 = K.c1*dy, t2 = K.c2*dy, t3 = K.c3*dy, t4 = K.c4*dy;
            const float4* row = tile + xr * WW;
            #pragma unroll
            for (int yc = 0; yc < PSZ; yc++) {
                float d13v, d42v;
                dists_at(K, dxv[yc], t1, t2, t3, t4, d13v, d42v);
                float h0 = fast_h(d13v);
                float h1 = fast_h(d42v);
                float w0 = 1.0f - h0;
                float w1 = h0 * (1.0f - h1);
                float4 img = __ldg(row + yc);
                sw0 += w0; sw1 += w1;
                cn00 = fmaf(img.x, w0, cn00); cn01 = fmaf(img.x, w1, cn01);
                cn10 = fmaf(img.y, w0, cn10); cn11 = fmaf(img.y, w1, cn11);
                cn20 = fmaf(img.z, w0, cn20); cn21 = fmaf(img.z, w1, cn21);
                G00 = fmaf(w0, w0, G00); G11 = fmaf(w1, w1, G11); G01 = fmaf(w0, w1, G01);
            }
        }
        // reconstruct eliminated terms
        float sw2 = 64.0f - sw0 - sw1;
        float G02 = sw0 - G00 - G01;
        float G12 = sw1 - G01 - G11;
        float G22 = sw2 - G02 - G12;
        float i0 = 1.0f / (sw0 + 1e-10f);
        float i1 = 1.0f / (sw1 + 1e-10f);
        float i2 = 1.0f / (sw2 + 1e-10f);
        float Sc[3] = {S.x, S.y, S.z};
        float n0a[3] = {cn00, cn10, cn20};
        float n1a[3] = {cn01, cn11, cn21};
        score = 0.0f;
        #pragma unroll
        for (int c = 0; c < 3; c++) {
            float n0 = n0a[c], n1 = n1a[c];
            float n2 = Sc[c] - n0 - n1;
            float c0 = n0*i0, c1 = n1*i1, c2 = n2*i2;
            float quad = c0*c0*G00 + c1*c1*G11 + c2*c2*G22
                       + 2.0f*(c0*c1*G01 + c0*c2*G02 + c1*c2*G12);
            score += quad - 2.0f*(c0*n0 + c1*n1 + c2*n2);
        }
    }
    sLoss[tid] = score;
    __syncthreads();

    if (valid && q == 0) {
        int best = 0;
        float bl = sLoss[lp * NV];
        #pragma unroll
        for (int k = 1; k < NV; k++) {
            float v = sLoss[lp * NV + k];
            if (v < bl) { bl = v; best = k; }
        }
        g_params[(b*5 + ip) * NPP + pp] = p[ip] + cand_range(ip, best);
    }
}

__global__ void k_final() {
    int P = blockIdx.x * blockDim.x + threadIdx.x;
    if (P >= NPTOT) return;
    int b = P / NPP, pp = P - b * NPP;
    int hp = pp / HPN, wp = pp - hp * HPN;

    float cp[5];
    #pragma unroll
    for (int j = 0; j < 5; j++) cp[j] = g_params[(b*5 + j) * NPP + pp];
    Cand K = make_cand(cp);
    const float4* tile = g_xr4 + b * NPIX + hp * WW + wp;

    float dxv[PSZ];
    #pragma unroll
    for (int yc = 0; yc < PSZ; yc++)
        dxv[yc] = (-1.0f + (float)yc * (2.0f/7.0f)) - K.x0;

    // pass 1: wedge sums + color numerators
    float sw[3] = {0,0,0};
    float cn[3][3] = {{0,0,0},{0,0,0},{0,0,0}};
    #pragma unroll 1
    for (int xr = 0; xr < PSZ; xr++) {
        float dy = (-1.0f + (float)xr * (2.0f/7.0f)) - K.y0;
        float t1 = K.c1*dy, t2 = K.c2*dy, t3 = K.c3*dy, t4 = K.c4*dy;
        const float4* row = tile + xr * WW;
        #pragma unroll
        for (int yc = 0; yc < PSZ; yc++) {
            float d13v, d42v;
            dists_at(K, dxv[yc], t1, t2, t3, t4, d13v, d42v);
            float h0 = fast_h(d13v);
            float h1 = fast_h(d42v);
            float w0 = 1.0f - h0, w1 = h0 * (1.0f - h1), w2 = h0 * h1;
            float4 img = __ldg(row + yc);
            sw[0] += w0; sw[1] += w1; sw[2] += w2;
            cn[0][0] = fmaf(img.x,w0,cn[0][0]); cn[0][1] = fmaf(img.x,w1,cn[0][1]); cn[0][2] = fmaf(img.x,w2,cn[0][2]);
            cn[1][0] = fmaf(img.y,w0,cn[1][0]); cn[1][1] = fmaf(img.y,w1,cn[1][1]); cn[1][2] = fmaf(img.y,w2,cn[1][2]);
            cn[2][0] = fmaf(img.z,w0,cn[2][0]); cn[2][1] = fmaf(img.z,w1,cn[2][1]); cn[2][2] = fmaf(img.z,w2,cn[2][2]);
        }
    }
    float col[3][3];
    #pragma unroll
    for (int k = 0; k < 3; k++) {
        float inv = 1.0f / (sw[k] + 1e-10f);
        col[0][k] = cn[0][k] * inv;
        col[1][k] = cn[1][k] * inv;
        col[2][k] = cn[2][k] * inv;
    }

    // pass 2: reconstruct patches + boundary map, scatter-add (fold)
    #pragma unroll 1
    for (int xr = 0; xr < PSZ; xr++) {
        float dy = (-1.0f + (float)xr * (2.0f/7.0f)) - K.y0;
        float t1 = K.c1*dy, t2 = K.c2*dy, t3 = K.c3*dy, t4 = K.c4*dy;
        int hh = xr + hp;
        #pragma unroll
        for (int yc = 0; yc < PSZ; yc++) {
            float d13v, d42v;
            dists_at(K, dxv[yc], t1, t2, t3, t4, d13v, d42v);
            float h0 = fast_h(d13v);
            float h1 = fast_h(d42v);
            float w0 = 1.0f - h0, w1 = h0 * (1.0f - h1), w2 = h0 * h1;
            int opix = hh * WW + yc + wp;
            #pragma unroll
            for (int c = 0; c < 3; c++) {
                float pv = w0*col[c][0] + w1*col[c][1] + w2*col[c][2];
                atomicAdd(&g_smoothed[(b*3 + c) * NPIX + opix], pv);
            }
            float d1 = d13v, d2 = d42v;
            float mad = (d1 < 0.0f) ? -d1
                      : ((d2 < 0.0f) ? fminf(d1, -d2) : fminf(d1, d2));
            float r = mad * 20.0f;
            float lb = 1.0f / (1.0f + r * r);
            atomicAdd(&g_gb[b * NPIX + opix], lb);
        }
    }
}

__global__ void k_post1(const float* __restrict__ fbw, const float* __restrict__ fiw) {
    int t = blockIdx.x * 256 + threadIdx.x;
    int b = t >> 12, pix = t & (NPIX - 1);
    int h = pix >> 6, w = pix & 63;
    int ch = min(min(h + 1, HH - h), PSZ);
    int cw = min(min(w + 1, WW - w), PSZ);
    float inv = 1.0f / (float)(ch * cw);

    float sm0 = g_smoothed[(b*3 + 0) * NPIX + pix] * inv;
    float sm1 = g_smoothed[(b*3 + 1) * NPIX + pix] * inv;
    float sm2 = g_smoothed[(b*3 + 2) * NPIX + pix] * inv;
    float yi = sm0 * fiw[0] + sm1 * fiw[1] + sm2 * fiw[2];
    float gbv = g_gb[t] * inv;
    float yb = gbv * fbw[0] + gbv * fbw[1] + gbv * fbw[2];
    g_yi[t] = yi;
    g_yb[t] = yb;

    __shared__ float sA[256], sB[256];
    sA[threadIdx.x] = yb; sB[threadIdx.x] = yb * yb;
    __syncthreads();
    for (int s = 128; s > 0; s >>= 1) {
        if (threadIdx.x < s) { sA[threadIdx.x] += sA[threadIdx.x+s]; sB[threadIdx.x] += sB[threadIdx.x+s]; }
        __syncthreads();
    }
    if (threadIdx.x == 0) { atomicAdd(&g_stats[6], sA[0]); atomicAdd(&g_stats[7], sB[0]); }
    __syncthreads();
    sA[threadIdx.x] = yi; sB[threadIdx.x] = yi * yi;
    __syncthreads();
    for (int s = 128; s > 0; s >>= 1) {
        if (threadIdx.x < s) { sA[threadIdx.x] += sA[threadIdx.x+s]; sB[threadIdx.x] += sB[threadIdx.x+s]; }
        __syncthreads();
    }
    if (threadIdx.x == 0) { atomicAdd(&g_stats[8], sA[0]); atomicAdd(&g_stats[9], sB[0]); }
}

__global__ void k_out(float* __restrict__ out,
                      const float* __restrict__ fbg, const float* __restrict__ fbb,
                      const float* __restrict__ fig, const float* __restrict__ fib) {
    int t = blockIdx.x * 256 + threadIdx.x;
    float mb = g_stats[6] * (1.0f / NSTAT);
    float vb = g_stats[7] * (1.0f / NSTAT) - mb * mb;
    float nb = fbg[0] * (g_yb[t] - mb) * rsqrtf(vb + 1e-5f) + fbb[0];
    out[t] = silu(nb);

    float mi = g_stats[8] * (1.0f / NSTAT);
    float vi = g_stats[9] * (1.0f / NSTAT) - mi * mi;
    float ni = fig[0] * (g_yi[t] - mi) * rsqrtf(vi + 1e-5f) + fib[0];
    out[NBATCH * NPIX + t] = silu(ni);
}

// ---------------- launch ----------------
extern "C" void kernel_launch(void* const* d_in, const int* in_sizes, int n_in,
                              void* d_out, int out_size) {
    const float* x   = (const float*)d_in[0];
    const float* rw  = (const float*)d_in[1];
    const float* rg  = (const float*)d_in[2];
    const float* rb  = (const float*)d_in[3];
    const float* fbw = (const float*)d_in[4];
    const float* fbg = (const float*)d_in[5];
    const float* fbb = (const float*)d_in[6];
    const float* fiw = (const float*)d_in[7];
    const float* fig = (const float*)d_in[8];
    const float* fib = (const float*)d_in[9];
    float* out = (float*)d_out;

    k_zero<<<64, 256>>>();
    k_conv<<<NBATCH * 3 * 16, 256>>>(x, rw);
    k_bnsilu<<<32, 256>>>(rg, rb);
    k_psum<<<(NPTOT + 255) / 256, 256>>>();
    for (int i = 0; i < 5; i++)
        k_step<<<(NPTOT + 7) / 8, 248>>>(i);
    k_final<<<(NPTOT + 255) / 256, 256>>>();
    k_post1<<<32, 256>>>(fbw, fiw);
    k_out<<<32, 256>>>(out, fbg, fbb, fig, fib);
}